// round 16
// baseline (speedup 1.0000x reference)
#include <cuda_runtime.h>
#include <math.h>

#define T_STEPS 100
#define MDIM 16
#define NDIM 16
#define H1D  2560      // W1 rows, GRU input dim
#define H2D  1024
#define HIDD 5120
#define NBLK 444       // exactly 3 blocks/SM on 148 SMs
#define NTHR 256
#define NWARP (NBLK * (NTHR/32))   // 3552 warps

// ---------------- persistent device state ----------------
__device__ float g_l1[H1D];
__device__ float g_hbuf[2][HIDD];
__device__ float g_l2[H2D];
__device__ float g_KG[MDIM * NDIM];
__device__ float g_m1x[2][MDIM];
__device__ float g_m1y[2][NDIM];
__device__ float g_spp[2][MDIM];
__device__ unsigned g_count;
__device__ volatile unsigned g_gen;

// Whh quantized + BIASED: stored hi = (s16 ^ 0x8000), lo = (s8 ^ 0x80)
// w ~= S_hh[j*3+g] * (s16 + s8/256); row = j*3+g   (~236 MB statics)
__device__ unsigned short Whh_hi[(size_t)HIDD * 3 * HIDD];   // 157.3 MB
__device__ unsigned char  Whh_lo[(size_t)HIDD * 3 * HIDD];   //  78.6 MB
__device__ float          S_hh[HIDD * 3];

// ---------------- quantize + repack Whh (biased storage, r15-proven) ----
__global__ void quant_hh_kernel(const float* __restrict__ src) {
    const int j = blockIdx.x, g = blockIdx.y;
    const float4* s = (const float4*)(src + ((size_t)g * HIDD + j) * HIDD); // 1280 float4
    const size_t drow = ((size_t)j * 3 + g) * HIDD;
    __shared__ float red[256];
    float mx = 0.f;
    for (int k = threadIdx.x; k < HIDD / 4; k += 256) {
        float4 v = s[k];
        mx = fmaxf(mx, fmaxf(fmaxf(fabsf(v.x), fabsf(v.y)), fmaxf(fabsf(v.z), fabsf(v.w))));
    }
    red[threadIdx.x] = mx;
    __syncthreads();
    for (int o = 128; o > 0; o >>= 1) {
        if (threadIdx.x < o) red[threadIdx.x] = fmaxf(red[threadIdx.x], red[threadIdx.x + o]);
        __syncthreads();
    }
    float m = red[0];
    float sc  = (m > 0.f) ? m / 32767.0f : 1.0f;
    float inv = (m > 0.f) ? 32767.0f / m : 0.0f;
    if (threadIdx.x == 0) S_hh[j * 3 + g] = sc;

    uint4* hrow = (uint4*)(Whh_hi + drow);   // 640 uint4 (8 biased u16 each)
    uint2* lrow = (uint2*)(Whh_lo + drow);   // 640 uint2 (8 biased u8 each)
    for (int k8 = threadIdx.x; k8 < HIDD / 8; k8 += 256) {
        float4 a = s[2 * k8], b = s[2 * k8 + 1];
        float f[8] = {a.x, a.y, a.z, a.w, b.x, b.y, b.z, b.w};
        unsigned hs[8], ls[8];
#pragma unroll
        for (int i = 0; i < 8; ++i) {
            float ff = f[i] * inv;
            float hq = rintf(ff);
            float d  = (ff - hq) * 256.0f;
            float lq = fminf(fmaxf(rintf(d), -128.0f), 127.0f);
            hs[i] = ((unsigned)(unsigned short)(short)hq) ^ 0x8000u;   // biased
            ls[i] = ((unsigned)(unsigned char)(signed char)lq) ^ 0x80u; // biased
        }
        uint4 hv;
        hv.x = hs[0] | (hs[1] << 16);
        hv.y = hs[2] | (hs[3] << 16);
        hv.z = hs[4] | (hs[5] << 16);
        hv.w = hs[6] | (hs[7] << 16);
        uint2 lv;
        lv.x = ls[0] | (ls[1] << 8) | (ls[2] << 16) | (ls[3] << 24);
        lv.y = ls[4] | (ls[5] << 8) | (ls[6] << 16) | (ls[7] << 24);
        hrow[k8] = hv;
        lrow[k8] = lv;
    }
}

__global__ void init_kernel(const float* __restrict__ h0) {
    int i = blockIdx.x * blockDim.x + threadIdx.x;
    if (i < HIDD) g_hbuf[0][i] = h0[i];
    if (i == 0) { g_count = 0; g_gen = 0; }
}

// ---------------- grid-wide spin barrier (r1/r7/r15-proven) ----------------
__device__ __forceinline__ void gsync(unsigned target) {
    __syncthreads();
    if (threadIdx.x == 0) {
        __threadfence();
        if (atomicAdd(&g_count, 1u) == gridDim.x - 1) {
            atomicExch(&g_count, 0u);
            __threadfence();
            g_gen = target;
        } else {
            while (g_gen < target) { __nanosleep(64); }
        }
        __threadfence();
    }
    __syncthreads();
}

__device__ __forceinline__ float wredsum(float v) {
#pragma unroll
    for (int o = 16; o > 0; o >>= 1) v += __shfl_xor_sync(0xffffffffu, v, o);
    return v;
}

__device__ __forceinline__ float sigmoidf_(float x) {
    return 1.0f / (1.0f + __expf(-x));
}

// ---- I2F-free decode: PRMT magic-number + exact subtract (r15-proven) ----
__device__ __forceinline__ float dec8p(uint4 h, uint2 l, float4 x0, float4 x1) {
    const float R  = 0.00390625f;     // 1/256
    const float CH = 8421376.0f;      // 2^23 + 2^15
    const float CL = 8388736.0f;      // 2^23 + 2^7
    float h0 = __uint_as_float(__byte_perm(h.x, 0x4B00u, 0x5410)) - CH;
    float h1 = __uint_as_float(__byte_perm(h.x, 0x4B00u, 0x5432)) - CH;
    float h2 = __uint_as_float(__byte_perm(h.y, 0x4B00u, 0x5410)) - CH;
    float h3 = __uint_as_float(__byte_perm(h.y, 0x4B00u, 0x5432)) - CH;
    float h4 = __uint_as_float(__byte_perm(h.z, 0x4B00u, 0x5410)) - CH;
    float h5 = __uint_as_float(__byte_perm(h.z, 0x4B00u, 0x5432)) - CH;
    float h6 = __uint_as_float(__byte_perm(h.w, 0x4B00u, 0x5410)) - CH;
    float h7 = __uint_as_float(__byte_perm(h.w, 0x4B00u, 0x5432)) - CH;
    float l0 = __uint_as_float(__byte_perm(l.x, 0x4B00u, 0x5440)) - CL;
    float l1 = __uint_as_float(__byte_perm(l.x, 0x4B00u, 0x5441)) - CL;
    float l2 = __uint_as_float(__byte_perm(l.x, 0x4B00u, 0x5442)) - CL;
    float l3 = __uint_as_float(__byte_perm(l.x, 0x4B00u, 0x5443)) - CL;
    float l4 = __uint_as_float(__byte_perm(l.y, 0x4B00u, 0x5440)) - CL;
    float l5 = __uint_as_float(__byte_perm(l.y, 0x4B00u, 0x5441)) - CL;
    float l6 = __uint_as_float(__byte_perm(l.y, 0x4B00u, 0x5442)) - CL;
    float l7 = __uint_as_float(__byte_perm(l.y, 0x4B00u, 0x5443)) - CL;
    float w0 = fmaf(l0, R, h0);
    float w1 = fmaf(l1, R, h1);
    float w2 = fmaf(l2, R, h2);
    float w3 = fmaf(l3, R, h3);
    float w4 = fmaf(l4, R, h4);
    float w5 = fmaf(l5, R, h5);
    float w6 = fmaf(l6, R, h6);
    float w7 = fmaf(l7, R, h7);
    float acc = w0 * x0.x;
    acc = fmaf(w1, x0.y, acc);
    acc = fmaf(w2, x0.z, acc);
    acc = fmaf(w3, x0.w, acc);
    acc = fmaf(w4, x1.x, acc);
    acc = fmaf(w5, x1.y, acc);
    acc = fmaf(w6, x1.z, acc);
    acc = fmaf(w7, x1.w, acc);
    return acc;
}

__global__ void __launch_bounds__(NTHR, 3)
knet_kernel(const float* __restrict__ y,  const float* __restrict__ F,
            const float* __restrict__ Hm, const float* __restrict__ m1_0,
            const float* __restrict__ W1, const float* __restrict__ b1,
            const float* __restrict__ Wih, const float* __restrict__ bih,
            const float* __restrict__ bhh,
            const float* __restrict__ W2, const float* __restrict__ b2,
            const float* __restrict__ W3, const float* __restrict__ b3,
            float* __restrict__ out)
{
    const int tid  = threadIdx.x;
    const int lane = tid & 31;
    const int wid  = blockIdx.x * (NTHR / 32) + (tid >> 5);  // 0..3551

    // prefix-range work assignment (SM-balanced to ~3%)
    const int lr0 = (int)((long long)wid * H1D / NWARP);         // l1 rows
    const int lr1 = (int)((long long)(wid + 1) * H1D / NWARP);
    const int eb0 = (int)((long long)wid * HIDD / NWARP);        // GRU elements
    const int eb1 = (int)((long long)(wid + 1) * HIDD / NWARP);
    const int cr0 = (int)((long long)wid * H2D / NWARP);         // W2 rows
    const int cr1 = (int)((long long)(wid + 1) * H2D / NWARP);
    const int dr0 = (int)((long long)wid * (MDIM * NDIM) / NWARP); // W3 rows
    const int dr1 = (int)((long long)(wid + 1) * (MDIM * NDIM) / NWARP);

    unsigned lg = 0;

    __shared__ float s_post[16], s_spold[16], s_m1x[16], s_spnew[16];
    __shared__ float s_d[16], s_e[16], s_kin[32], s_nrm[2];

    for (int t = 0; t < T_STEPS; ++t) {
        const int cur = t & 1, prev = cur ^ 1;

        // ================= Phase A: post update + state + kin + l1 ==========
        if (tid < 16) {
            float p, sp;
            if (t == 0) {
                p = m1_0[tid]; sp = m1_0[tid];
            } else {
                float acc = g_m1x[prev][tid];
#pragma unroll
                for (int k = 0; k < 16; ++k)
                    acc += g_KG[tid * 16 + k] * (y[k * T_STEPS + (t - 1)] - g_m1y[prev][k]);
                p  = acc;
                sp = g_spp[prev][tid];
                if (blockIdx.x == 0) out[tid * T_STEPS + (t - 1)] = p;
            }
            s_post[tid] = p; s_spold[tid] = sp;
        }
        __syncthreads();
        if (tid < 16) {
            float mx = 0.f, sn = 0.f;
#pragma unroll
            for (int k = 0; k < 16; ++k) {
                float f = F[tid * 16 + k];
                mx += f * s_post[k];
                sn += f * s_spold[k];
            }
            s_m1x[tid] = mx; s_spnew[tid] = sn;
        }
        __syncthreads();
        if (tid < 16) {
            float my = 0.f, ob = 0.f;
#pragma unroll
            for (int k = 0; k < 16; ++k) {
                float h = Hm[tid * 16 + k];
                my += h * s_m1x[k];
                ob += h * s_spnew[k];
            }
            s_d[tid] = s_post[tid] - s_spold[tid];
            s_e[tid] = y[tid * T_STEPS + t] - ob;
            if (blockIdx.x == 0) {
                g_m1x[cur][tid] = s_m1x[tid];
                g_m1y[cur][tid] = my;
                g_spp[cur][tid] = s_spnew[tid];
            }
        }
        __syncthreads();
        if (tid == 0) {
            float nd = 0.f, ne = 0.f;
#pragma unroll
            for (int k = 0; k < 16; ++k) { nd += s_d[k] * s_d[k]; ne += s_e[k] * s_e[k]; }
            s_nrm[0] = fmaxf(sqrtf(nd), 1e-12f);
            s_nrm[1] = fmaxf(sqrtf(ne), 1e-12f);
        }
        __syncthreads();
        if (tid < 32)
            s_kin[tid] = (tid < 16) ? s_d[tid] / s_nrm[0] : s_e[tid - 16] / s_nrm[1];
        __syncthreads();

        // l1 = relu(W1 @ kin + b1): prefix-range rows (0-1 per warp)
        for (int row = lr0; row < lr1; ++row) {
            float v = W1[row * 32 + lane] * s_kin[lane];
            v = wredsum(v);
            if (lane == 0) g_l1[row] = fmaxf(v + b1[row], 0.0f);
        }
        ++lg; gsync(lg);

        // ================= Phase B: fused GRU GEMV (prefix-range elems) =====
        //   Wih: fp32; Whh: int24, PRMT magic decode -- arithmetic == r15
        {
            const float*  hold = g_hbuf[cur];     // t=0 -> slot 0 holds h0
            float*        hnew = g_hbuf[prev];
            const float4* l1v  = (const float4*)g_l1;
            const float4* hv   = (const float4*)hold;
            for (int j = eb0; j < eb1; ++j) {
                float ar = 0.f, az = 0.f, an = 0.f;
                float br = 0.f, bz = 0.f, bn = 0.f;
                const float4* wr = (const float4*)(Wih + (size_t)(0 * HIDD + j) * H1D);
                const float4* wz = (const float4*)(Wih + (size_t)(1 * HIDD + j) * H1D);
                const float4* wn = (const float4*)(Wih + (size_t)(2 * HIDD + j) * H1D);
#pragma unroll 4
                for (int k = lane; k < H1D / 4; k += 32) {
                    float4 x = l1v[k];
                    float4 a = wr[k]; ar += a.x * x.x + a.y * x.y + a.z * x.z + a.w * x.w;
                    float4 b = wz[k]; az += b.x * x.x + b.y * x.y + b.z * x.z + b.w * x.w;
                    float4 c = wn[k]; an += c.x * x.x + c.y * x.y + c.z * x.z + c.w * x.w;
                }
                const uint4* hi_h = (const uint4*)(Whh_hi + (size_t)j * 3 * HIDD);  // 640 uint4/gate
                const uint2* lo_h = (const uint2*)(Whh_lo + (size_t)j * 3 * HIDD);  // 640 uint2/gate
#pragma unroll 2
                for (int k = lane; k < HIDD / 8; k += 32) {
                    float4 x0 = hv[2 * k], x1 = hv[2 * k + 1];
                    br += dec8p(hi_h[k],        lo_h[k],        x0, x1);
                    bz += dec8p(hi_h[640 + k],  lo_h[640 + k],  x0, x1);
                    bn += dec8p(hi_h[1280 + k], lo_h[1280 + k], x0, x1);
                }
                ar = wredsum(ar); az = wredsum(az); an = wredsum(an);
                br = wredsum(br); bz = wredsum(bz); bn = wredsum(bn);
                if (lane == 0) {
                    float hr = br * S_hh[j * 3 + 0];
                    float hz = bz * S_hh[j * 3 + 1];
                    float hn = bn * S_hh[j * 3 + 2];
                    float r  = sigmoidf_(ar + bih[j]            + hr + bhh[j]);
                    float z  = sigmoidf_(az + bih[HIDD + j]     + hz + bhh[HIDD + j]);
                    float nn = tanhf   (an + bih[2 * HIDD + j] + r * (hn + bhh[2 * HIDD + j]));
                    hnew[j] = (1.0f - z) * nn + z * hold[j];
                }
            }
        }
        ++lg; gsync(lg);

        // ================= Phase C: l2 = relu(W2 @ h_new + b2) ==============
        for (int row = cr0; row < cr1; ++row) {
            const float4* hvn = (const float4*)g_hbuf[prev];   // h_new
            const float4* w   = (const float4*)(W2 + (size_t)row * HIDD);
            float acc = 0.f;
#pragma unroll 4
            for (int k = lane; k < HIDD / 4; k += 32) {
                float4 a = w[k]; float4 x = hvn[k];
                acc += a.x * x.x + a.y * x.y + a.z * x.z + a.w * x.w;
            }
            acc = wredsum(acc);
            if (lane == 0) g_l2[row] = fmaxf(acc + b2[row], 0.0f);
        }
        ++lg; gsync(lg);

        // ================= Phase D: KG = W3 @ l2 + b3 =======================
        for (int row = dr0; row < dr1; ++row) {
            const float4* lv = (const float4*)g_l2;
            const float4* w  = (const float4*)(W3 + (size_t)row * H2D);
            float acc = 0.f;
#pragma unroll
            for (int k = lane; k < H2D / 4; k += 32) {
                float4 a = w[k]; float4 x = lv[k];
                acc += a.x * x.x + a.y * x.y + a.z * x.z + a.w * x.w;
            }
            acc = wredsum(acc);
            if (lane == 0) g_KG[row] = acc + b3[row];
        }
        ++lg; gsync(lg);
    }

    // ---- final output column (post update of step T-1) ----
    if (blockIdx.x == 0 && tid < 16) {
        const int pl = (T_STEPS - 1) & 1;
        float acc = g_m1x[pl][tid];
#pragma unroll
        for (int k = 0; k < 16; ++k)
            acc += g_KG[tid * 16 + k] * (y[k * T_STEPS + (T_STEPS - 1)] - g_m1y[pl][k]);
        out[tid * T_STEPS + (T_STEPS - 1)] = acc;
    }
}

extern "C" void kernel_launch(void* const* d_in, const int* in_sizes, int n_in,
                              void* d_out, int out_size) {
    const float* y    = (const float*)d_in[0];
    const float* F    = (const float*)d_in[1];
    const float* Hm   = (const float*)d_in[2];
    const float* m1_0 = (const float*)d_in[3];
    const float* h0   = (const float*)d_in[4];
    const float* W1   = (const float*)d_in[5];
    const float* b1   = (const float*)d_in[6];
    const float* Wih  = (const float*)d_in[7];
    const float* bih  = (const float*)d_in[8];
    const float* Whh  = (const float*)d_in[9];
    const float* bhh  = (const float*)d_in[10];
    const float* W2   = (const float*)d_in[11];
    const float* b2   = (const float*)d_in[12];
    const float* W3   = (const float*)d_in[13];
    const float* b3   = (const float*)d_in[14];
    float* out = (float*)d_out;

    quant_hh_kernel<<<dim3(HIDD, 3), 256>>>(Whh);
    init_kernel<<<20, 256>>>(h0);
    knet_kernel<<<NBLK, NTHR>>>(y, F, Hm, m1_0, W1, b1, Wih, bih,
                                bhh, W2, b2, W3, b3, out);
}